// round 4
// baseline (speedup 1.0000x reference)
#include <cuda_runtime.h>
#include <math.h>

// Problem constants (fixed by the reference: B=8192, V=8, J=32)
constexpr int BB = 8192;
constexpr int VV = 8;
constexpr int JJ = 32;
constexpr int PAIRS = BB * VV;                    // 65536 (b,v) problems
constexpr int WARPS_PER_BLOCK = 8;                // one block = one batch's 8 views
constexpr int NBLOCKS = PAIRS / WARPS_PER_BLOCK;  // 8192
constexpr float SCALE_KPS = 0.1f;
constexpr float THRESHOLD = 100.0f;
constexpr float ALPHA = 0.1f;
constexpr float T_BETA = 63.095734448019324f;     // 100^0.9
constexpr double FIX = 262144.0;                  // 2^18 fixed-point scale

__device__ unsigned long long g_accum = 0ull;     // fixed-point grid sum
__device__ unsigned int g_ticket = 0u;            // completion counter

__global__ __launch_bounds__(WARPS_PER_BLOCK * 32)
void qpl_fused(const float* __restrict__ Kmat,
               const float* __restrict__ cam,
               const float* __restrict__ kps,
               const float* __restrict__ init,
               float* __restrict__ out) {
    const int t = threadIdx.x;
    const int warp_in_blk = t >> 5;
    const int lane = t & 31;
    const int pair = blockIdx.x * WARPS_PER_BLOCK + warp_in_blk;  // b*V + v

    // ---- cooperative staging: one block = one batch (8 views, shared kps) ----
    __shared__ float4 sC[VV][3];       // cam rows as float4      (96 floats)
    __shared__ float  sK[VV][12];      // K padded 9 -> 12 floats
    __shared__ float  sP[JJ * 3];      // world keypoints          (96 floats)
    __shared__ float  sm[WARPS_PER_BLOCK];

    if (t < 24) {
        // cam: 24 float4 coalesced
        reinterpret_cast<float4*>(sC)[t] =
            reinterpret_cast<const float4*>(cam + (size_t)blockIdx.x * 96)[t];
    } else if (t < 96) {
        // K: 72 scalar floats -> padded smem layout
        const int i = t - 24;
        sK[i / 9][i % 9] = Kmat[(size_t)blockIdx.x * 72 + i];
    } else if (t < 192) {
        // kps: 96 scalar floats (loaded ONCE per block, shared by 8 warps)
        const int i = t - 96;
        sP[i] = kps[(size_t)blockIdx.x * 96 + i];
    }
    // init keypoints: direct coalesced per-lane load (bulk of the bytes)
    const float2 ik = reinterpret_cast<const float2*>(init)[(size_t)pair * JJ + lane];
    __syncthreads();

    // ---- per-joint projection, two-stage (matches reference einsum order) ----
    // lane j handles joint j (J == 32). kps read: stride-3 -> conflict-free.
    const float X = sP[lane * 3 + 0];
    const float Y = sP[lane * 3 + 1];
    const float Z = sP[lane * 3 + 2];

    const float4 c0 = sC[warp_in_blk][0];
    const float4 c1 = sC[warp_in_blk][1];
    const float4 c2 = sC[warp_in_blk][2];
    const float* kk = sK[warp_in_blk];   // warp-uniform broadcast LDS

    // camera coords: cam[3x4] @ [X,Y,Z,1]
    const float cx = c0.x * X + c0.y * Y + c0.z * Z + c0.w;
    const float cy = c1.x * X + c1.y * Y + c1.z * Z + c1.w;
    const float cz = c2.x * X + c2.y * Y + c2.z * Z + c2.w;
    // image coords: K[3x3] @ cam_pt
    const float px = kk[0] * cx + kk[1] * cy + kk[2] * cz;
    const float py = kk[3] * cx + kk[4] * cy + kk[5] * cz;
    const float pz = kk[6] * cx + kk[7] * cy + kk[8] * cz;

    const float inv_z = __frcp_rn(pz);
    const float u = px * inv_z;
    const float w = py * inv_z;

    float pn2 = u * u + w * w;              // proj fro-norm^2 contribution
    float in2 = ik.x * ik.x + ik.y * ik.y;  // init fro-norm^2 contribution

    float d0 = (u - ik.x) * SCALE_KPS; d0 = d0 * d0;
    float d1 = (w - ik.y) * SCALE_KPS; d1 = d1 * d1;
    if (d0 > THRESHOLD) d0 = __powf(d0, ALPHA) * T_BETA;
    if (d1 > THRESHOLD) d1 = __powf(d1, ALPHA) * T_BETA;
    float ls = d0 + d1;

    // ---- warp butterfly reduce (3 values) ----
#pragma unroll
    for (int o = 16; o; o >>= 1) {
        pn2 += __shfl_xor_sync(0xFFFFFFFFu, pn2, o);
        in2 += __shfl_xor_sync(0xFFFFFFFFu, in2, o);
        ls  += __shfl_xor_sync(0xFFFFFFFFu, ls,  o);
    }

    if (lane == 0) {
        const float penal = fabsf(__fsqrt_rn(pn2 * __frcp_rn(in2)) - 1.0f);
        sm[warp_in_blk] = penal * ls * 0.5f;
    }
    __syncthreads();

    if (t == 0) {
        float s = 0.0f;
#pragma unroll
        for (int i = 0; i < WARPS_PER_BLOCK; i++) s += sm[i];
        // order-invariant integer accumulation => deterministic grid sum
        const long long q = __double2ll_rn((double)s * FIX);
        atomicAdd(&g_accum, (unsigned long long)q);
        __threadfence();
        const unsigned int tk = atomicAdd(&g_ticket, 1u);
        if (tk == (unsigned int)(NBLOCKS - 1)) {
            const unsigned long long total = atomicAdd(&g_accum, 0ull);
            const double mean = ((double)(long long)total) / FIX / (double)PAIRS;
            out[0] = (float)mean;
            atomicExch(&g_accum, 0ull);
            __threadfence();
            atomicExch(&g_ticket, 0u);
        }
    }
}

extern "C" void kernel_launch(void* const* d_in, const int* in_sizes, int n_in,
                              void* d_out, int out_size) {
    const float* Kmat = (const float*)d_in[0];  // [B,V,3,3]
    const float* cam  = (const float*)d_in[1];  // [B,V,3,4]
    const float* kps  = (const float*)d_in[2];  // [B,J,3]
    const float* init = (const float*)d_in[3];  // [B,V,J,2]
    float* out = (float*)d_out;

    qpl_fused<<<NBLOCKS, WARPS_PER_BLOCK * 32>>>(Kmat, cam, kps, init, out);
}

// round 5
// speedup vs baseline: 1.5016x; 1.5016x over previous
#include <cuda_runtime.h>
#include <math.h>

// Problem constants (fixed by the reference: B=8192, V=8, J=32)
constexpr int BB = 8192;
constexpr int VV = 8;
constexpr int JJ = 32;
constexpr int PAIRS = BB * VV;                     // 65536 (b,v) problems
constexpr int WARPS_PER_BLOCK = 8;
constexpr int PAIRS_PER_BLOCK = WARPS_PER_BLOCK * 2;  // 2 pairs per warp
constexpr int NBLOCKS = PAIRS / PAIRS_PER_BLOCK;   // 4096
constexpr float SCALE_KPS = 0.1f;
constexpr float THRESHOLD = 100.0f;
constexpr float ALPHA = 0.1f;
constexpr float T_BETA = 63.095734448019324f;      // 100^0.9
constexpr double FIX = 262144.0;                   // 2^18 fixed-point scale

__device__ unsigned long long g_accum = 0ull;      // fixed-point grid sum
__device__ unsigned int g_ticket = 0u;             // completion counter

__global__ __launch_bounds__(WARPS_PER_BLOCK * 32)
void qpl_fused(const float* __restrict__ Kmat,
               const float* __restrict__ cam,
               const float* __restrict__ kps,
               const float* __restrict__ init,
               float* __restrict__ out) {
    const int t = threadIdx.x;
    const int warp = t >> 5;
    const int lane = t & 31;
    const int half = lane >> 4;     // which pair within the warp
    const int sub  = lane & 15;     // lane within 16-lane group; handles joints 2*sub, 2*sub+1
    const int pair = blockIdx.x * PAIRS_PER_BLOCK + warp * 2 + half;
    const int b = pair >> 3;

    // ---- loads (all direct, coalesced / uniform-broadcast) ----
    // init: [B,V,J,2] -> 16 float4 per pair; lane sub covers joints 2sub, 2sub+1
    const float4 ik4 = reinterpret_cast<const float4*>(init)[(size_t)pair * 16 + sub];
    // kps: [B,J,3] -> 6 floats (2 joints) per lane, 8-byte aligned
    const float2* kp2 = reinterpret_cast<const float2*>(kps + (size_t)b * (JJ * 3) + sub * 6);
    const float2 p0 = kp2[0], p1 = kp2[1], p2 = kp2[2];
    // cam rows (16-group-uniform): pair*48B is 16B aligned
    const float4* C = reinterpret_cast<const float4*>(cam + (size_t)pair * 12);
    const float4 c0 = C[0], c1 = C[1], c2 = C[2];
    // K (16-group-uniform scalars)
    const float* Kp = Kmat + (size_t)pair * 9;
    const float k0 = Kp[0], k1 = Kp[1], k2 = Kp[2];
    const float k3 = Kp[3], k4 = Kp[4], k5 = Kp[5];
    const float k6 = Kp[6], k7 = Kp[7], k8 = Kp[8];

    float pn2 = 0.0f, in2 = 0.0f, ls = 0.0f;

    // ---- joint 2*sub ----
    {
        const float X = p0.x, Y = p0.y, Z = p1.x;
        const float cx = c0.x * X + c0.y * Y + c0.z * Z + c0.w;
        const float cy = c1.x * X + c1.y * Y + c1.z * Z + c1.w;
        const float cz = c2.x * X + c2.y * Y + c2.z * Z + c2.w;
        const float px = k0 * cx + k1 * cy + k2 * cz;
        const float py = k3 * cx + k4 * cy + k5 * cz;
        const float pz = k6 * cx + k7 * cy + k8 * cz;
        const float iz = __frcp_rn(pz);
        const float u = px * iz, w = py * iz;
        pn2 += u * u + w * w;
        in2 += ik4.x * ik4.x + ik4.y * ik4.y;
        float d0 = (u - ik4.x) * SCALE_KPS; d0 = d0 * d0;
        float d1 = (w - ik4.y) * SCALE_KPS; d1 = d1 * d1;
        if (d0 > THRESHOLD) d0 = __powf(d0, ALPHA) * T_BETA;
        if (d1 > THRESHOLD) d1 = __powf(d1, ALPHA) * T_BETA;
        ls += d0 + d1;
    }
    // ---- joint 2*sub+1 ----
    {
        const float X = p1.y, Y = p2.x, Z = p2.y;
        const float cx = c0.x * X + c0.y * Y + c0.z * Z + c0.w;
        const float cy = c1.x * X + c1.y * Y + c1.z * Z + c1.w;
        const float cz = c2.x * X + c2.y * Y + c2.z * Z + c2.w;
        const float px = k0 * cx + k1 * cy + k2 * cz;
        const float py = k3 * cx + k4 * cy + k5 * cz;
        const float pz = k6 * cx + k7 * cy + k8 * cz;
        const float iz = __frcp_rn(pz);
        const float u = px * iz, w = py * iz;
        pn2 += u * u + w * w;
        in2 += ik4.z * ik4.z + ik4.w * ik4.w;
        float d0 = (u - ik4.z) * SCALE_KPS; d0 = d0 * d0;
        float d1 = (w - ik4.w) * SCALE_KPS; d1 = d1 * d1;
        if (d0 > THRESHOLD) d0 = __powf(d0, ALPHA) * T_BETA;
        if (d1 > THRESHOLD) d1 = __powf(d1, ALPHA) * T_BETA;
        ls += d0 + d1;
    }

    // ---- segmented butterfly reduce within each 16-lane group ----
#pragma unroll
    for (int o = 8; o; o >>= 1) {
        pn2 += __shfl_xor_sync(0xFFFFFFFFu, pn2, o);
        in2 += __shfl_xor_sync(0xFFFFFFFFu, in2, o);
        ls  += __shfl_xor_sync(0xFFFFFFFFu, ls,  o);
    }

    __shared__ float sm[PAIRS_PER_BLOCK];
    if (sub == 0) {
        const float penal = fabsf(__fsqrt_rn(pn2 * __frcp_rn(in2)) - 1.0f);
        sm[warp * 2 + half] = penal * ls * 0.5f;
    }
    __syncthreads();

    if (t == 0) {
        float s = 0.0f;
#pragma unroll
        for (int i = 0; i < PAIRS_PER_BLOCK; i++) s += sm[i];
        // order-invariant integer accumulation => deterministic grid sum
        const long long q = __double2ll_rn((double)s * FIX);
        atomicAdd(&g_accum, (unsigned long long)q);
        __threadfence();
        const unsigned int tk = atomicAdd(&g_ticket, 1u);
        if (tk == (unsigned int)(NBLOCKS - 1)) {
            const unsigned long long total = atomicAdd(&g_accum, 0ull);
            const double mean = ((double)(long long)total) / FIX / (double)PAIRS;
            out[0] = (float)mean;
            atomicExch(&g_accum, 0ull);
            __threadfence();
            atomicExch(&g_ticket, 0u);
        }
    }
}

extern "C" void kernel_launch(void* const* d_in, const int* in_sizes, int n_in,
                              void* d_out, int out_size) {
    const float* Kmat = (const float*)d_in[0];  // [B,V,3,3]
    const float* cam  = (const float*)d_in[1];  // [B,V,3,4]
    const float* kps  = (const float*)d_in[2];  // [B,J,3]
    const float* init = (const float*)d_in[3];  // [B,V,J,2]
    float* out = (float*)d_out;

    qpl_fused<<<NBLOCKS, WARPS_PER_BLOCK * 32>>>(Kmat, cam, kps, init, out);
}

// round 6
// speedup vs baseline: 1.7065x; 1.1364x over previous
#include <cuda_runtime.h>
#include <math.h>

// Problem constants (fixed by the reference: B=8192, V=8, J=32)
constexpr int BB = 8192;
constexpr int VV = 8;
constexpr int JJ = 32;
constexpr int PAIRS = BB * VV;                        // 65536 (b,v) problems
constexpr int WARPS_PER_BLOCK = 8;
constexpr int PAIRS_PER_WARP = 4;                     // 8-lane segments
constexpr int PAIRS_PER_BLOCK = WARPS_PER_BLOCK * PAIRS_PER_WARP;  // 32
constexpr int NBLOCKS = PAIRS / PAIRS_PER_BLOCK;      // 2048
constexpr float SCALE_KPS = 0.1f;
constexpr float THRESHOLD = 100.0f;
constexpr float ALPHA = 0.1f;
constexpr float T_BETA = 63.095734448019324f;         // 100^0.9
constexpr double FIX = 262144.0;                      // 2^18 fixed-point scale

__device__ unsigned long long g_accum = 0ull;         // fixed-point grid sum
__device__ unsigned int g_ticket = 0u;                // completion counter

struct Acc { float pn2, in2, ls; };

__device__ __forceinline__ void do_joint(
    float X, float Y, float Z, float ix, float iy,
    const float4& c0, const float4& c1, const float4& c2,
    float k0, float k1, float k2, float k3, float k4,
    float k5, float k6, float k7, float k8, Acc& a)
{
    const float cx = c0.x * X + c0.y * Y + c0.z * Z + c0.w;
    const float cy = c1.x * X + c1.y * Y + c1.z * Z + c1.w;
    const float cz = c2.x * X + c2.y * Y + c2.z * Z + c2.w;
    const float px = k0 * cx + k1 * cy + k2 * cz;
    const float py = k3 * cx + k4 * cy + k5 * cz;
    const float pz = k6 * cx + k7 * cy + k8 * cz;
    const float iz = __frcp_rn(pz);
    const float u = px * iz, w = py * iz;
    a.pn2 += u * u + w * w;
    a.in2 += ix * ix + iy * iy;
    float d0 = (u - ix) * SCALE_KPS; d0 = d0 * d0;
    float d1 = (w - iy) * SCALE_KPS; d1 = d1 * d1;
    if (d0 > THRESHOLD) d0 = __powf(d0, ALPHA) * T_BETA;
    if (d1 > THRESHOLD) d1 = __powf(d1, ALPHA) * T_BETA;
    a.ls += d0 + d1;
}

__global__ __launch_bounds__(WARPS_PER_BLOCK * 32)
void qpl_fused(const float* __restrict__ Kmat,
               const float* __restrict__ cam,
               const float* __restrict__ kps,
               const float* __restrict__ init,
               float* __restrict__ out) {
    const int t = threadIdx.x;
    const int warp = t >> 5;
    const int lane = t & 31;
    const int grp = lane >> 3;      // which of 4 pairs in this warp
    const int sub = lane & 7;       // lane within 8-lane group; handles joints 4*sub..4*sub+3
    const int pair = blockIdx.x * PAIRS_PER_BLOCK + warp * PAIRS_PER_WARP + grp;
    const int b = pair >> 3;        // 4 consecutive pairs share one batch (4 | 8)

    // ---- loads: all 16B-aligned vector or group-uniform broadcast ----
    // init: joints 4sub..4sub+3 -> 2 float4
    const float4* ikp = reinterpret_cast<const float4*>(init) + (size_t)pair * 16 + sub * 2;
    const float4 ia = ikp[0], ib = ikp[1];
    // kps: 12 floats (4 joints), 48B-aligned -> 3 float4 (warp-broadcast across groups)
    const float4* kp4 = reinterpret_cast<const float4*>(kps + (size_t)b * (JJ * 3) + sub * 12);
    const float4 q0 = kp4[0], q1 = kp4[1], q2 = kp4[2];
    // cam rows (group-uniform)
    const float4* C = reinterpret_cast<const float4*>(cam + (size_t)pair * 12);
    const float4 c0 = C[0], c1 = C[1], c2 = C[2];
    // K (group-uniform scalars)
    const float* Kp = Kmat + (size_t)pair * 9;
    const float k0 = Kp[0], k1 = Kp[1], k2 = Kp[2];
    const float k3 = Kp[3], k4 = Kp[4], k5 = Kp[5];
    const float k6 = Kp[6], k7 = Kp[7], k8 = Kp[8];

    Acc a = {0.0f, 0.0f, 0.0f};
    // 4 independent joint chains -> ILP to hide MUFU/LDG latency
    do_joint(q0.x, q0.y, q0.z, ia.x, ia.y, c0, c1, c2, k0,k1,k2,k3,k4,k5,k6,k7,k8, a);
    do_joint(q0.w, q1.x, q1.y, ia.z, ia.w, c0, c1, c2, k0,k1,k2,k3,k4,k5,k6,k7,k8, a);
    do_joint(q1.z, q1.w, q2.x, ib.x, ib.y, c0, c1, c2, k0,k1,k2,k3,k4,k5,k6,k7,k8, a);
    do_joint(q2.y, q2.z, q2.w, ib.z, ib.w, c0, c1, c2, k0,k1,k2,k3,k4,k5,k6,k7,k8, a);

    // ---- segmented butterfly reduce within each 8-lane group ----
#pragma unroll
    for (int o = 4; o; o >>= 1) {
        a.pn2 += __shfl_xor_sync(0xFFFFFFFFu, a.pn2, o);
        a.in2 += __shfl_xor_sync(0xFFFFFFFFu, a.in2, o);
        a.ls  += __shfl_xor_sync(0xFFFFFFFFu, a.ls,  o);
    }

    __shared__ float sm[PAIRS_PER_BLOCK];
    if (sub == 0) {
        const float penal = fabsf(__fsqrt_rn(a.pn2 * __frcp_rn(a.in2)) - 1.0f);
        sm[warp * PAIRS_PER_WARP + grp] = penal * a.ls * 0.5f;
    }
    __syncthreads();

    // warp 0 reduces the 32 per-pair results
    if (warp == 0) {
        float s = sm[lane];
#pragma unroll
        for (int o = 16; o; o >>= 1) s += __shfl_xor_sync(0xFFFFFFFFu, s, o);
        if (lane == 0) {
            // order-invariant integer accumulation => deterministic grid sum
            const long long q = __double2ll_rn((double)s * FIX);
            atomicAdd(&g_accum, (unsigned long long)q);
            __threadfence();
            const unsigned int tk = atomicAdd(&g_ticket, 1u);
            if (tk == (unsigned int)(NBLOCKS - 1)) {
                const unsigned long long total = atomicAdd(&g_accum, 0ull);
                const double mean = ((double)(long long)total) / FIX / (double)PAIRS;
                out[0] = (float)mean;
                atomicExch(&g_accum, 0ull);
                __threadfence();
                atomicExch(&g_ticket, 0u);
            }
        }
    }
}

extern "C" void kernel_launch(void* const* d_in, const int* in_sizes, int n_in,
                              void* d_out, int out_size) {
    const float* Kmat = (const float*)d_in[0];  // [B,V,3,3]
    const float* cam  = (const float*)d_in[1];  // [B,V,3,4]
    const float* kps  = (const float*)d_in[2];  // [B,J,3]
    const float* init = (const float*)d_in[3];  // [B,V,J,2]
    float* out = (float*)d_out;

    qpl_fused<<<NBLOCKS, WARPS_PER_BLOCK * 32>>>(Kmat, cam, kps, init, out);
}